// round 3
// baseline (speedup 1.0000x reference)
#include <cuda_runtime.h>
#include <cstdint>
#include <math.h>

#define N_NODES 50000
#define FEAT    512
#define HH      64      // HEADS*HID
#define HEADS   8
#define NCLS    7

// ---------------- scratch (device globals: no allocations allowed) ----------
__device__ float g_xl1[N_NODES * HH];     // layer-1 left projection  [N,64]
__device__ float g_xr1[N_NODES * HH];     // layer-1 right projection [N,64]
__device__ float g_acc1[N_NODES * HH];    // sum_e w * xl[src]        [N,64]
__device__ float g_den1[N_NODES * HEADS]; // sum_e w                  [N,8]
__device__ float g_xl2[N_NODES * 8];      // layer-2 left proj, padded to 8
__device__ float g_xr2[N_NODES * 8];      // layer-2 right proj, padded to 8
__device__ float g_acc2[N_NODES * 8];     // slots 0..6: sum w*xl2, slot 7: sum w
__device__ int   g_idx64;                 // 1 if edge buffer is int64, 0 if int32

// ---------------- helpers ---------------------------------------------------
__device__ __forceinline__ float lrelu(float v) {
    return fmaxf(v, 0.2f * v);   // leaky relu, slope 0.2
}

__device__ __forceinline__ void red_add_f32(float* p, float v) {
    asm volatile("red.global.add.f32 [%0], %1;" :: "l"(p), "f"(v) : "memory");
}

__device__ __forceinline__ void red_add_v4(float* p, float a, float b, float c, float d) {
    asm volatile("red.global.add.v4.f32 [%0], {%1,%2,%3,%4};"
                 :: "l"(p), "f"(a), "f"(b), "f"(c), "f"(d) : "memory");
}

// Decode edge endpoints, robust to int32 vs int64 edge buffers.
__device__ __forceinline__ void load_edge(const void* ei, int E, int eid,
                                          int idx64, int& s, int& d) {
    if (eid < E) {
        if (idx64) {
            s = (int)((const long long*)ei)[eid];
            d = (int)((const long long*)ei)[E + eid];
        } else {
            s = ((const int*)ei)[eid];
            d = ((const int*)ei)[E + eid];
        }
    } else {
        s = d = eid - E;   // self-loop
    }
}

// ---------------- K_detect: probe edge-index dtype ---------------------------
// If data is int64 with values < 2^31, every odd 32-bit word (high half) is 0.
// If data is int32 random indices in [0, 50000), 64 consecutive odd words being
// all zero has probability ~(1/50000)^64 ~ 0.
__global__ void detect_kernel(const int* __restrict__ ei_words) {
    int all_zero = 1;
    #pragma unroll
    for (int i = 0; i < 64; i++) {
        if (ei_words[2 * i + 1] != 0) { all_zero = 0; break; }
    }
    g_idx64 = all_zero;
}

// ---------------- K0: zero scratch accumulators -----------------------------
__global__ void zero_kernel() {
    int i = blockIdx.x * blockDim.x + threadIdx.x;
    float4 z = make_float4(0.f, 0.f, 0.f, 0.f);
    if (i < N_NODES * 16) reinterpret_cast<float4*>(g_acc1)[i] = z;   // N*64 floats
    if (i < N_NODES * 2) {
        reinterpret_cast<float4*>(g_den1)[i] = z;                     // N*8 floats
        reinterpret_cast<float4*>(g_acc2)[i] = z;                     // N*8 floats
    }
}

// ---------------- K1: layer-1 projections (fused xl & xr GEMM) ---------------
// block = 128 threads, handles 16 rows of x. tid<64 -> Wl column tid,
// tid>=64 -> Wr column tid-64.
__global__ __launch_bounds__(128) void proj1_kernel(
    const float* __restrict__ x,
    const float* __restrict__ Wl, const float* __restrict__ bl,
    const float* __restrict__ Wr, const float* __restrict__ br)
{
    __shared__ float sx[16 * FEAT];           // 32 KB
    const int tid  = threadIdx.x;
    const int row0 = blockIdx.x * 16;

    const float4* xin = reinterpret_cast<const float4*>(x + (size_t)row0 * FEAT);
    float4* s4 = reinterpret_cast<float4*>(sx);
    #pragma unroll
    for (int j = 0; j < 16; j++) s4[tid + j * 128] = xin[tid + j * 128];
    __syncthreads();

    const float* Wp = (tid < HH) ? (Wl + tid) : (Wr + (tid - HH));
    float acc[16];
    #pragma unroll
    for (int r = 0; r < 16; r++) acc[r] = 0.f;

    #pragma unroll 4
    for (int k = 0; k < FEAT; k += 4) {
        float w0 = Wp[(k + 0) * HH];
        float w1 = Wp[(k + 1) * HH];
        float w2 = Wp[(k + 2) * HH];
        float w3 = Wp[(k + 3) * HH];
        #pragma unroll
        for (int r = 0; r < 16; r++) {
            float4 xv = *reinterpret_cast<const float4*>(&sx[r * FEAT + k]);
            acc[r] += xv.x * w0 + xv.y * w1 + xv.z * w2 + xv.w * w3;
        }
    }

    float bias = (tid < HH) ? bl[tid] : br[tid - HH];
    float* dst = (tid < HH) ? (g_xl1 + tid) : (g_xr1 + (tid - HH));
    #pragma unroll
    for (int r = 0; r < 16; r++) dst[(size_t)(row0 + r) * HH] = acc[r] + bias;
}

// ---------------- K2: layer-1 edge pass --------------------------------------
// 8 threads per edge (one per head). Computes e, w=exp(e) and scatters
// w*xl[src] (2x red.v4) + w into the per-head denominator (1x scalar red).
__global__ void edge1_kernel(const void* __restrict__ ei, int E,
                             const float* __restrict__ att)
{
    int gid = blockIdx.x * blockDim.x + threadIdx.x;
    int eid = gid >> 3;
    int h   = gid & 7;
    int E2  = E + N_NODES;
    if (eid >= E2) return;

    int s, d;
    load_edge(ei, E, eid, g_idx64, s, d);
    if ((unsigned)s >= N_NODES || (unsigned)d >= N_NODES) return;  // safety

    const float4* xa = reinterpret_cast<const float4*>(g_xl1 + (size_t)s * HH + h * 8);
    const float4* xb = reinterpret_cast<const float4*>(g_xr1 + (size_t)d * HH + h * 8);
    float4 a0 = xa[0], a1 = xa[1];
    float4 b0 = xb[0], b1 = xb[1];

    const float4* at = reinterpret_cast<const float4*>(att + h * 8);
    float4 t0 = at[0], t1 = at[1];

    float e = lrelu(a0.x + b0.x) * t0.x + lrelu(a0.y + b0.y) * t0.y
            + lrelu(a0.z + b0.z) * t0.z + lrelu(a0.w + b0.w) * t0.w
            + lrelu(a1.x + b1.x) * t1.x + lrelu(a1.y + b1.y) * t1.y
            + lrelu(a1.z + b1.z) * t1.z + lrelu(a1.w + b1.w) * t1.w;

    float w = expf(e);

    float* accp = g_acc1 + (size_t)d * HH + h * 8;
    red_add_v4(accp,     w * a0.x, w * a0.y, w * a0.z, w * a0.w);
    red_add_v4(accp + 4, w * a1.x, w * a1.y, w * a1.z, w * a1.w);
    red_add_f32(g_den1 + (size_t)d * HEADS + h, w);
}

// ---------------- K3: layer-1 finalize (softmax div + bias + ELU) + proj2 ----
__global__ __launch_bounds__(256) void fin1_kernel(
    const float* __restrict__ bias1,
    const float* __restrict__ Wl2, const float* __restrict__ bl2,
    const float* __restrict__ Wr2, const float* __restrict__ br2)
{
    __shared__ float sh[4][HH];
    __shared__ float sWl[HH * NCLS], sWr[HH * NCLS];
    const int tid = threadIdx.x;
    for (int i = tid; i < HH * NCLS; i += 256) { sWl[i] = Wl2[i]; sWr[i] = Wr2[i]; }

    const int node0 = blockIdx.x * 4;
    const int ln = tid >> 6;
    const int f  = tid & 63;
    const int n  = node0 + ln;

    float v = g_acc1[(size_t)n * HH + f] / g_den1[(size_t)n * HEADS + (f >> 3)] + bias1[f];
    sh[ln][f] = (v > 0.f) ? v : expm1f(v);     // ELU
    __syncthreads();

    if (f < 16) {
        int  c    = f & 7;
        bool left = (f < 8);
        float out = 0.f;
        if (c < NCLS) {
            const float* W = left ? sWl : sWr;
            float acc = left ? bl2[c] : br2[c];
            #pragma unroll
            for (int k = 0; k < HH; k++) acc += sh[ln][k] * W[k * NCLS + c];
            out = acc;
        }
        (left ? g_xl2 : g_xr2)[(size_t)n * 8 + c] = out;
    }
}

// ---------------- K4: layer-2 edge pass --------------------------------------
__global__ void edge2_kernel(const void* __restrict__ ei, int E,
                             const float* __restrict__ att2)
{
    int eid = blockIdx.x * blockDim.x + threadIdx.x;
    int E2 = E + N_NODES;
    if (eid >= E2) return;

    int s, d;
    load_edge(ei, E, eid, g_idx64, s, d);
    if ((unsigned)s >= N_NODES || (unsigned)d >= N_NODES) return;  // safety

    const float4* xa = reinterpret_cast<const float4*>(g_xl2 + (size_t)s * 8);
    const float4* xb = reinterpret_cast<const float4*>(g_xr2 + (size_t)d * 8);
    float4 p0 = xa[0], p1 = xa[1];
    float4 q0 = xb[0], q1 = xb[1];

    float e = lrelu(p0.x + q0.x) * att2[0] + lrelu(p0.y + q0.y) * att2[1]
            + lrelu(p0.z + q0.z) * att2[2] + lrelu(p0.w + q0.w) * att2[3]
            + lrelu(p1.x + q1.x) * att2[4] + lrelu(p1.y + q1.y) * att2[5]
            + lrelu(p1.z + q1.z) * att2[6];

    float w = expf(e);

    float* accp = g_acc2 + (size_t)d * 8;
    red_add_v4(accp,     w * p0.x, w * p0.y, w * p0.z, w * p0.w);
    red_add_v4(accp + 4, w * p1.x, w * p1.y, w * p1.z, w);       // slot 7: denominator
}

// ---------------- K5: final divide + bias + log_softmax ----------------------
__global__ void final_kernel(float* __restrict__ out, const float* __restrict__ bias2)
{
    int n = blockIdx.x * blockDim.x + threadIdx.x;
    if (n >= N_NODES) return;

    const float4* ap = reinterpret_cast<const float4*>(g_acc2 + (size_t)n * 8);
    float4 a0 = ap[0], a1 = ap[1];
    float inv = 1.f / a1.w;

    float v[NCLS];
    v[0] = a0.x * inv + bias2[0];
    v[1] = a0.y * inv + bias2[1];
    v[2] = a0.z * inv + bias2[2];
    v[3] = a0.w * inv + bias2[3];
    v[4] = a1.x * inv + bias2[4];
    v[5] = a1.y * inv + bias2[5];
    v[6] = a1.z * inv + bias2[6];

    float m = v[0];
    #pragma unroll
    for (int c = 1; c < NCLS; c++) m = fmaxf(m, v[c]);
    float ssum = 0.f;
    #pragma unroll
    for (int c = 0; c < NCLS; c++) ssum += expf(v[c] - m);
    float l = m + logf(ssum);
    #pragma unroll
    for (int c = 0; c < NCLS; c++) out[(size_t)n * NCLS + c] = v[c] - l;
}

// ---------------- launch -----------------------------------------------------
extern "C" void kernel_launch(void* const* d_in, const int* in_sizes, int n_in,
                              void* d_out, int out_size)
{
    const float* x     = (const float*)d_in[0];
    const void*  ei    = d_in[1];
    const float* Wl1   = (const float*)d_in[2];
    const float* bl1   = (const float*)d_in[3];
    const float* Wr1   = (const float*)d_in[4];
    const float* br1   = (const float*)d_in[5];
    const float* att1  = (const float*)d_in[6];
    const float* bias1 = (const float*)d_in[7];
    const float* Wl2   = (const float*)d_in[8];
    const float* bl2   = (const float*)d_in[9];
    const float* Wr2   = (const float*)d_in[10];
    const float* br2   = (const float*)d_in[11];
    const float* att2  = (const float*)d_in[12];
    const float* bias2 = (const float*)d_in[13];

    const int E  = in_sizes[1] / 2;          // 1,600,000
    const int E2 = E + N_NODES;              // with self-loops

    detect_kernel<<<1, 1>>>((const int*)ei);
    zero_kernel<<<(N_NODES * 16 + 255) / 256, 256>>>();
    proj1_kernel<<<N_NODES / 16, 128>>>(x, Wl1, bl1, Wr1, br1);
    edge1_kernel<<<((size_t)E2 * 8 + 255) / 256, 256>>>(ei, E, att1);
    fin1_kernel<<<N_NODES / 4, 256>>>(bias1, Wl2, bl2, Wr2, br2);
    edge2_kernel<<<(E2 + 255) / 256, 256>>>(ei, E, att2);
    final_kernel<<<(N_NODES + 255) / 256, 256>>>((float*)d_out, bias2);
}

// round 4
// speedup vs baseline: 1.0083x; 1.0083x over previous
#include <cuda_runtime.h>
#include <cstdint>
#include <math.h>

#define N_NODES 50000
#define FEAT    512
#define HH      64      // HEADS*HID
#define HEADS   8
#define NCLS    7

// ---------------- scratch (device globals: no allocations allowed) ----------
__device__ float g_xl1[N_NODES * HH];     // layer-1 left projection  [N,64]
__device__ float g_xr1[N_NODES * HH];     // layer-1 right projection [N,64]
__device__ float g_acc1[N_NODES * HH];    // sum_e w * xl[src]        [N,64]
__device__ float g_den1[N_NODES * HEADS]; // sum_e w                  [N,8]
__device__ float g_xl2[N_NODES * 8];      // layer-2 left proj, padded to 8
__device__ float g_xr2[N_NODES * 8];      // layer-2 right proj, padded to 8
__device__ float g_acc2[N_NODES * 8];     // slots 0..6: sum w*xl2, slot 7: sum w
__device__ int   g_idx64;                 // 1 if edge buffer is int64, 0 if int32

typedef unsigned long long u64;

// ---------------- helpers ---------------------------------------------------
__device__ __forceinline__ float lrelu(float v) {
    return fmaxf(v, 0.2f * v);   // leaky relu, slope 0.2
}

__device__ __forceinline__ void red_add_f32(float* p, float v) {
    asm volatile("red.global.add.f32 [%0], %1;" :: "l"(p), "f"(v) : "memory");
}

__device__ __forceinline__ void red_add_v4(float* p, float a, float b, float c, float d) {
    asm volatile("red.global.add.v4.f32 [%0], {%1,%2,%3,%4};"
                 :: "l"(p), "f"(a), "f"(b), "f"(c), "f"(d) : "memory");
}

// packed dual fp32 FMA (Blackwell f32x2): acc.lo += a.lo*b.lo ; acc.hi += a.hi*b.hi
__device__ __forceinline__ void fma_x2(u64& acc, u64 a, u64 b) {
    asm("fma.rn.f32x2 %0, %1, %2, %0;" : "+l"(acc) : "l"(a), "l"(b));
}

__device__ __forceinline__ u64 pack2(float lo, float hi) {
    u64 r;
    asm("mov.b64 %0, {%1, %2};" : "=l"(r) : "f"(lo), "f"(hi));
    return r;
}

__device__ __forceinline__ float2 unpack2(u64 v) {
    float2 r;
    asm("mov.b64 {%0, %1}, %2;" : "=f"(r.x), "=f"(r.y) : "l"(v));
    return r;
}

// Decode edge endpoints, robust to int32 vs int64 edge buffers.
__device__ __forceinline__ void load_edge(const void* ei, int E, int eid,
                                          int idx64, int& s, int& d) {
    if (eid < E) {
        if (idx64) {
            s = (int)((const long long*)ei)[eid];
            d = (int)((const long long*)ei)[E + eid];
        } else {
            s = ((const int*)ei)[eid];
            d = ((const int*)ei)[E + eid];
        }
    } else {
        s = d = eid - E;   // self-loop
    }
}

// ---------------- K0: zero scratch accumulators (+ dtype probe) -------------
__global__ void zero_kernel(const int* __restrict__ ei_words) {
    int i = blockIdx.x * blockDim.x + threadIdx.x;
    if (i == 0) {
        // probe edge-index dtype: int64 indices < 2^31 -> all odd words zero
        int all_zero = 1;
        #pragma unroll
        for (int j = 0; j < 64; j++)
            if (ei_words[2 * j + 1] != 0) { all_zero = 0; break; }
        g_idx64 = all_zero;
    }
    float4 z = make_float4(0.f, 0.f, 0.f, 0.f);
    if (i < N_NODES * 16) reinterpret_cast<float4*>(g_acc1)[i] = z;   // N*64 floats
    if (i < N_NODES * 2) {
        reinterpret_cast<float4*>(g_den1)[i] = z;                     // N*8 floats
        reinterpret_cast<float4*>(g_acc2)[i] = z;                     // N*8 floats
    }
}

// ---------------- K1: layer-1 projections (fused xl & xr, f32x2 FMA) ---------
// block = 128 threads, handles 16 rows of x. tid<64 -> Wl column tid,
// tid>=64 -> Wr column tid-64. Inner loop uses packed fma.rn.f32x2:
// acc01 accumulates k%4 in {0,1}, acc23 accumulates k%4 in {2,3}.
__global__ __launch_bounds__(128) void proj1_kernel(
    const float* __restrict__ x,
    const float* __restrict__ Wl, const float* __restrict__ bl,
    const float* __restrict__ Wr, const float* __restrict__ br)
{
    __shared__ __align__(16) float sx[16 * FEAT];   // 32 KB
    const int tid  = threadIdx.x;
    const int row0 = blockIdx.x * 16;

    // stage 16 full rows of x into smem (coalesced float4)
    const float4* xin = reinterpret_cast<const float4*>(x + (size_t)row0 * FEAT);
    float4* s4 = reinterpret_cast<float4*>(sx);
    #pragma unroll
    for (int j = 0; j < 16; j++) s4[tid + j * 128] = xin[tid + j * 128];
    __syncthreads();

    const float* Wp = (tid < HH) ? (Wl + tid) : (Wr + (tid - HH));
    u64 acc01[16], acc23[16];
    #pragma unroll
    for (int r = 0; r < 16; r++) { acc01[r] = 0ull; acc23[r] = 0ull; }

    #pragma unroll 2
    for (int k = 0; k < FEAT; k += 4) {
        float w0 = Wp[(k + 0) * HH];
        float w1 = Wp[(k + 1) * HH];
        float w2 = Wp[(k + 2) * HH];
        float w3 = Wp[(k + 3) * HH];
        u64 w01 = pack2(w0, w1);
        u64 w23 = pack2(w2, w3);
        #pragma unroll
        for (int r = 0; r < 16; r++) {
            ulonglong2 xv = *reinterpret_cast<const ulonglong2*>(&sx[r * FEAT + k]);
            fma_x2(acc01[r], xv.x, w01);
            fma_x2(acc23[r], xv.y, w23);
        }
    }

    float bias = (tid < HH) ? bl[tid] : br[tid - HH];
    float* dst = (tid < HH) ? (g_xl1 + tid) : (g_xr1 + (tid - HH));
    #pragma unroll
    for (int r = 0; r < 16; r++) {
        float2 p = unpack2(acc01[r]);
        float2 q = unpack2(acc23[r]);
        dst[(size_t)(row0 + r) * HH] = (p.x + p.y) + (q.x + q.y) + bias;
    }
}

// ---------------- K2: layer-1 edge pass --------------------------------------
// Grid-stride loop; each thread keeps head h fixed so att lives in registers.
// Computes e, w=exp(e), scatters w*xl[src] (2x red.v4) + w (scalar red).
__global__ void edge1_kernel(const void* __restrict__ ei, int E,
                             const float* __restrict__ att)
{
    const int E2    = E + N_NODES;
    const int gid   = blockIdx.x * blockDim.x + threadIdx.x;
    const int h     = gid & 7;
    const int lanes = (gridDim.x * blockDim.x) >> 3;

    const float4* at = reinterpret_cast<const float4*>(att + h * 8);
    const float4 t0 = at[0], t1 = at[1];
    const int idx64 = g_idx64;

    for (int eid = gid >> 3; eid < E2; eid += lanes) {
        int s, d;
        load_edge(ei, E, eid, idx64, s, d);
        if ((unsigned)s >= N_NODES || (unsigned)d >= N_NODES) continue;  // safety

        const float4* xa = reinterpret_cast<const float4*>(g_xl1 + (size_t)s * HH + h * 8);
        const float4* xb = reinterpret_cast<const float4*>(g_xr1 + (size_t)d * HH + h * 8);
        float4 a0 = xa[0], a1 = xa[1];
        float4 b0 = xb[0], b1 = xb[1];

        float e = lrelu(a0.x + b0.x) * t0.x + lrelu(a0.y + b0.y) * t0.y
                + lrelu(a0.z + b0.z) * t0.z + lrelu(a0.w + b0.w) * t0.w
                + lrelu(a1.x + b1.x) * t1.x + lrelu(a1.y + b1.y) * t1.y
                + lrelu(a1.z + b1.z) * t1.z + lrelu(a1.w + b1.w) * t1.w;

        float w = expf(e);

        float* accp = g_acc1 + (size_t)d * HH + h * 8;
        red_add_v4(accp,     w * a0.x, w * a0.y, w * a0.z, w * a0.w);
        red_add_v4(accp + 4, w * a1.x, w * a1.y, w * a1.z, w * a1.w);
        red_add_f32(g_den1 + (size_t)d * HEADS + h, w);
    }
}

// ---------------- K3: layer-1 finalize (softmax div + bias + ELU) + proj2 ----
__global__ __launch_bounds__(256) void fin1_kernel(
    const float* __restrict__ bias1,
    const float* __restrict__ Wl2, const float* __restrict__ bl2,
    const float* __restrict__ Wr2, const float* __restrict__ br2)
{
    __shared__ float sh[4][HH];
    __shared__ float sWl[HH * NCLS], sWr[HH * NCLS];
    const int tid = threadIdx.x;
    for (int i = tid; i < HH * NCLS; i += 256) { sWl[i] = Wl2[i]; sWr[i] = Wr2[i]; }

    const int node0 = blockIdx.x * 4;
    const int ln = tid >> 6;
    const int f  = tid & 63;
    const int n  = node0 + ln;

    float v = g_acc1[(size_t)n * HH + f] / g_den1[(size_t)n * HEADS + (f >> 3)] + bias1[f];
    sh[ln][f] = (v > 0.f) ? v : expm1f(v);     // ELU
    __syncthreads();

    if (f < 16) {
        int  c    = f & 7;
        bool left = (f < 8);
        float out = 0.f;
        if (c < NCLS) {
            const float* W = left ? sWl : sWr;
            float acc = left ? bl2[c] : br2[c];
            #pragma unroll
            for (int k = 0; k < HH; k++) acc += sh[ln][k] * W[k * NCLS + c];
            out = acc;
        }
        (left ? g_xl2 : g_xr2)[(size_t)n * 8 + c] = out;
    }
}

// ---------------- K4: layer-2 edge pass --------------------------------------
// Grid-stride; att2 + idx64 hoisted into registers. Denominator packed in
// slot 7 of acc2.
__global__ void edge2_kernel(const void* __restrict__ ei, int E,
                             const float* __restrict__ att2)
{
    const int E2    = E + N_NODES;
    const int lanes = gridDim.x * blockDim.x;
    const int gid   = blockIdx.x * blockDim.x + threadIdx.x;

    float a2[NCLS];
    #pragma unroll
    for (int c = 0; c < NCLS; c++) a2[c] = att2[c];
    const int idx64 = g_idx64;

    for (int eid = gid; eid < E2; eid += lanes) {
        int s, d;
        load_edge(ei, E, eid, idx64, s, d);
        if ((unsigned)s >= N_NODES || (unsigned)d >= N_NODES) continue;  // safety

        const float4* xa = reinterpret_cast<const float4*>(g_xl2 + (size_t)s * 8);
        const float4* xb = reinterpret_cast<const float4*>(g_xr2 + (size_t)d * 8);
        float4 p0 = xa[0], p1 = xa[1];
        float4 q0 = xb[0], q1 = xb[1];

        float e = lrelu(p0.x + q0.x) * a2[0] + lrelu(p0.y + q0.y) * a2[1]
                + lrelu(p0.z + q0.z) * a2[2] + lrelu(p0.w + q0.w) * a2[3]
                + lrelu(p1.x + q1.x) * a2[4] + lrelu(p1.y + q1.y) * a2[5]
                + lrelu(p1.z + q1.z) * a2[6];

        float w = expf(e);

        float* accp = g_acc2 + (size_t)d * 8;
        red_add_v4(accp,     w * p0.x, w * p0.y, w * p0.z, w * p0.w);
        red_add_v4(accp + 4, w * p1.x, w * p1.y, w * p1.z, w);       // slot 7: denom
    }
}

// ---------------- K5: final divide + bias + log_softmax ----------------------
__global__ void final_kernel(float* __restrict__ out, const float* __restrict__ bias2)
{
    int n = blockIdx.x * blockDim.x + threadIdx.x;
    if (n >= N_NODES) return;

    const float4* ap = reinterpret_cast<const float4*>(g_acc2 + (size_t)n * 8);
    float4 a0 = ap[0], a1 = ap[1];
    float inv = 1.f / a1.w;

    float v[NCLS];
    v[0] = a0.x * inv + bias2[0];
    v[1] = a0.y * inv + bias2[1];
    v[2] = a0.z * inv + bias2[2];
    v[3] = a0.w * inv + bias2[3];
    v[4] = a1.x * inv + bias2[4];
    v[5] = a1.y * inv + bias2[5];
    v[6] = a1.z * inv + bias2[6];

    float m = v[0];
    #pragma unroll
    for (int c = 1; c < NCLS; c++) m = fmaxf(m, v[c]);
    float ssum = 0.f;
    #pragma unroll
    for (int c = 0; c < NCLS; c++) ssum += expf(v[c] - m);
    float l = m + logf(ssum);
    #pragma unroll
    for (int c = 0; c < NCLS; c++) out[(size_t)n * NCLS + c] = v[c] - l;
}

// ---------------- launch -----------------------------------------------------
extern "C" void kernel_launch(void* const* d_in, const int* in_sizes, int n_in,
                              void* d_out, int out_size)
{
    const float* x     = (const float*)d_in[0];
    const void*  ei    = d_in[1];
    const float* Wl1   = (const float*)d_in[2];
    const float* bl1   = (const float*)d_in[3];
    const float* Wr1   = (const float*)d_in[4];
    const float* br1   = (const float*)d_in[5];
    const float* att1  = (const float*)d_in[6];
    const float* bias1 = (const float*)d_in[7];
    const float* Wl2   = (const float*)d_in[8];
    const float* bl2   = (const float*)d_in[9];
    const float* Wr2   = (const float*)d_in[10];
    const float* br2   = (const float*)d_in[11];
    const float* att2  = (const float*)d_in[12];
    const float* bias2 = (const float*)d_in[13];

    const int E = in_sizes[1] / 2;           // 1,600,000

    zero_kernel<<<(N_NODES * 16 + 255) / 256, 256>>>((const int*)ei);
    proj1_kernel<<<N_NODES / 16, 128>>>(x, Wl1, bl1, Wr1, br1);
    edge1_kernel<<<1184, 256>>>(ei, E, att1);               // grid-stride, h fixed
    fin1_kernel<<<N_NODES / 4, 256>>>(bias1, Wl2, bl2, Wr2, br2);
    edge2_kernel<<<1184, 256>>>(ei, E, att2);               // grid-stride
    final_kernel<<<(N_NODES + 255) / 256, 256>>>((float*)d_out, bias2);
}

// round 6
// speedup vs baseline: 1.6706x; 1.6568x over previous
#include <cuda_runtime.h>
#include <cuda_bf16.h>
#include <cstdint>
#include <math.h>

#define N_NODES 50000
#define FEAT    512
#define HH      64      // HEADS*HID
#define HEADS   8
#define NCLS    7

typedef unsigned long long u64;
typedef unsigned int u32;

// ---------------- scratch (device globals: no allocations allowed) ----------
__device__ float g_xl1[N_NODES * HH];
__device__ float g_xr1[N_NODES * HH];
__device__ float g_acc1[N_NODES * HH];
__device__ float g_den1[N_NODES * HEADS];
__device__ float g_xl2[N_NODES * 8];
__device__ float g_xr2[N_NODES * 8];
__device__ float g_acc2[N_NODES * 8];
__device__ int   g_idx64;
// bf16 hi/lo images of B = [Wl | Wr], layout [n][k]: n in 0..127, k in 0..511
__device__ __nv_bfloat16 g_Bh[128 * FEAT];
__device__ __nv_bfloat16 g_Bl[128 * FEAT];

// ---------------- generic helpers -------------------------------------------
__device__ __forceinline__ float lrelu(float v) { return fmaxf(v, 0.2f * v); }

__device__ __forceinline__ void red_add_f32(float* p, float v) {
    asm volatile("red.global.add.f32 [%0], %1;" :: "l"(p), "f"(v) : "memory");
}
__device__ __forceinline__ void red_add_v4(float* p, float a, float b, float c, float d) {
    asm volatile("red.global.add.v4.f32 [%0], {%1,%2,%3,%4};"
                 :: "l"(p), "f"(a), "f"(b), "f"(c), "f"(d) : "memory");
}

__device__ __forceinline__ void load_edge(const void* ei, int E, int eid,
                                          int idx64, int& s, int& d) {
    if (eid < E) {
        if (idx64) {
            s = (int)((const long long*)ei)[eid];
            d = (int)((const long long*)ei)[E + eid];
        } else {
            s = ((const int*)ei)[eid];
            d = ((const int*)ei)[E + eid];
        }
    } else {
        s = d = eid - E;
    }
}

__device__ __forceinline__ u32 smem_u32(const void* p) {
    u32 a;
    asm("{ .reg .u64 t; cvta.to.shared.u64 t, %1; cvt.u32.u64 %0, t; }" : "=r"(a) : "l"(p));
    return a;
}

// ldmatrix: 4x 8x8 b16 tiles; lanes 0-7/8-15/16-23/24-31 give row addrs per tile
__device__ __forceinline__ void ldsm_x4(u32 addr, u32& r0, u32& r1, u32& r2, u32& r3) {
    asm volatile("ldmatrix.sync.aligned.m8n8.x4.shared.b16 {%0,%1,%2,%3}, [%4];"
                 : "=r"(r0), "=r"(r1), "=r"(r2), "=r"(r3) : "r"(addr));
}

// m16n8k16 row.col bf16 -> f32 accumulate
__device__ __forceinline__ void mma_bf16(float* c, const u32* a, const u32* b) {
    asm volatile("mma.sync.aligned.m16n8k16.row.col.f32.bf16.bf16.f32 "
                 "{%0,%1,%2,%3}, {%4,%5,%6,%7}, {%8,%9}, {%0,%1,%2,%3};"
                 : "+f"(c[0]), "+f"(c[1]), "+f"(c[2]), "+f"(c[3])
                 : "r"(a[0]), "r"(a[1]), "r"(a[2]), "r"(a[3]), "r"(b[0]), "r"(b[1]));
}

// ---------------- K0: zero accumulators (+ dtype probe) ----------------------
__global__ void zero_kernel(const int* __restrict__ ei_words) {
    int i = blockIdx.x * blockDim.x + threadIdx.x;
    if (i == 0) {
        int all_zero = 1;
        #pragma unroll
        for (int j = 0; j < 64; j++)
            if (ei_words[2 * j + 1] != 0) { all_zero = 0; break; }
        g_idx64 = all_zero;
    }
    float4 z = make_float4(0.f, 0.f, 0.f, 0.f);
    if (i < N_NODES * 16) reinterpret_cast<float4*>(g_acc1)[i] = z;
    if (i < N_NODES * 2) {
        reinterpret_cast<float4*>(g_den1)[i] = z;
        reinterpret_cast<float4*>(g_acc2)[i] = z;
    }
}

// ---------------- Kp: build bf16 hi/lo images of [Wl|Wr] as [n][k] ----------
__global__ void prepB_kernel(const float* __restrict__ Wl, const float* __restrict__ Wr) {
    int i = blockIdx.x * blockDim.x + threadIdx.x;   // 65536
    if (i >= 128 * FEAT) return;
    int n = i >> 9;          // 0..127
    int k = i & 511;
    float w = (n < HH) ? Wl[k * HH + n] : Wr[k * HH + (n - HH)];
    __nv_bfloat16 hi = __float2bfloat16(w);
    __nv_bfloat16 lo = __float2bfloat16(w - __bfloat162float(hi));
    g_Bh[i] = hi;
    g_Bl[i] = lo;
}

// ---------------- K1: proj1 via mma.sync bf16x3 ------------------------------
// CTA: 128 threads (4 warps, 2x2), tile M=64 x N=128, K chunked by 64.
// Warp w: rows (w&1)*32 .. +32, cols (w>>1)*64 .. +64.
#define ASTR 72                   // A smem row stride (bf16), 144B = 9*16B
#define BSTR 72
#define S_AH 0                    // 64*72*2  = 9216
#define S_AL 9216
#define S_BH 18432                // 128*72*2 = 18432
#define S_BL 36864
#define S_BIAS 55296              // 128 floats
#define PROJ_SMEM (55296 + 512)

__global__ __launch_bounds__(128) void proj1_kernel(
    const float* __restrict__ x,
    const float* __restrict__ bl, const float* __restrict__ br)
{
    extern __shared__ __align__(16) char smem[];
    const u32 sb = smem_u32(smem);
    const int tid  = threadIdx.x;
    const int lane = tid & 31;
    const int w    = tid >> 5;
    const int m0   = blockIdx.x * 64;

    ((float*)(smem + S_BIAS))[tid] = (tid < HH) ? bl[tid] : br[tid - HH];

    float acc[2][8][4];
    #pragma unroll
    for (int m = 0; m < 2; m++)
        #pragma unroll
        for (int t = 0; t < 8; t++)
            #pragma unroll
            for (int j = 0; j < 4; j++) acc[m][t][j] = 0.f;

    const int wr0 = (w & 1) * 32;
    const int nc0 = (w >> 1) * 64;
    const int r   = lane & 7;
    const int bq  = lane >> 3;
    // ldmatrix lane-address offsets (bytes), block order matches fragment order:
    // A tile(m,s): blocks (r0-7/k0-7)(r8-15/k0-7)(r0-7/k8-15)(r8-15/k8-15)
    const u32 offA = (u32)(((wr0 + (bq & 1) * 8 + r) * ASTR + (bq >> 1) * 8) * 2);
    // B tiles(t,t+1,s): blocks (t,k0-7)(t,k8-15)(t+1,k0-7)(t+1,k8-15), rows = n
    const u32 offB = (u32)(((nc0 + (bq >> 1) * 8 + r) * BSTR + (bq & 1) * 8) * 2);

    for (int c = 0; c < 8; c++) {
        // ---- stage A chunk 64x64: fp32 -> bf16 hi/lo
        #pragma unroll
        for (int i = 0; i < 8; i++) {
            int idx = tid + i * 128;           // 1024 float4s
            int row = idx >> 4;
            int kq  = (idx & 15) * 4;
            float4 v = make_float4(0.f, 0.f, 0.f, 0.f);
            if (m0 + row < N_NODES)
                v = *reinterpret_cast<const float4*>(x + (size_t)(m0 + row) * FEAT + c * 64 + kq);
            __nv_bfloat162 h01 = __floats2bfloat162_rn(v.x, v.y);
            __nv_bfloat162 h23 = __floats2bfloat162_rn(v.z, v.w);
            __nv_bfloat162 l01 = __floats2bfloat162_rn(v.x - __bfloat162float(h01.x),
                                                       v.y - __bfloat162float(h01.y));
            __nv_bfloat162 l23 = __floats2bfloat162_rn(v.z - __bfloat162float(h23.x),
                                                       v.w - __bfloat162float(h23.y));
            u32 off = (u32)((row * ASTR + kq) * 2);   // 8B aligned
            *reinterpret_cast<__nv_bfloat162*>(smem + S_AH + off)     = h01;
            *reinterpret_cast<__nv_bfloat162*>(smem + S_AH + off + 4) = h23;
            *reinterpret_cast<__nv_bfloat162*>(smem + S_AL + off)     = l01;
            *reinterpret_cast<__nv_bfloat162*>(smem + S_AL + off + 4) = l23;
        }
        // ---- stage B chunk 128x64 (pre-converted, [n][k])
        #pragma unroll
        for (int i = 0; i < 8; i++) {
            int idx = tid + i * 128;           // 1024 uint4s per image
            int n   = idx >> 3;
            int kq  = (idx & 7) * 8;
            uint4 vh = *reinterpret_cast<const uint4*>(g_Bh + (size_t)n * FEAT + c * 64 + kq);
            uint4 vl = *reinterpret_cast<const uint4*>(g_Bl + (size_t)n * FEAT + c * 64 + kq);
            u32 off = (u32)((n * BSTR + kq) * 2);     // 16B aligned
            *reinterpret_cast<uint4*>(smem + S_BH + off) = vh;
            *reinterpret_cast<uint4*>(smem + S_BL + off) = vl;
        }
        __syncthreads();

        // ---- MMA: 4 k16 steps, 3 terms
        #pragma unroll
        for (int s = 0; s < 4; s++) {
            u32 ah[2][4], al[2][4], bh[8][2], blo[8][2];
            #pragma unroll
            for (int m = 0; m < 2; m++) {
                u32 ao = offA + (u32)((m * 16 * ASTR + s * 16) * 2);
                ldsm_x4(sb + S_AH + ao, ah[m][0], ah[m][1], ah[m][2], ah[m][3]);
                ldsm_x4(sb + S_AL + ao, al[m][0], al[m][1], al[m][2], al[m][3]);
            }
            #pragma unroll
            for (int t = 0; t < 8; t += 2) {
                u32 bo = offB + (u32)((t * 8 * BSTR + s * 16) * 2);
                ldsm_x4(sb + S_BH + bo, bh[t][0], bh[t][1], bh[t + 1][0], bh[t + 1][1]);
                ldsm_x4(sb + S_BL + bo, blo[t][0], blo[t][1], blo[t + 1][0], blo[t + 1][1]);
            }
            #pragma unroll
            for (int m = 0; m < 2; m++)
                #pragma unroll
                for (int t = 0; t < 8; t++) {
                    mma_bf16(acc[m][t], ah[m], bh[t]);
                    mma_bf16(acc[m][t], ah[m], blo[t]);
                    mma_bf16(acc[m][t], al[m], bh[t]);
                }
        }
        __syncthreads();
    }

    // ---- epilogue: c0,c1 -> (row, col..col+1); c2,c3 -> (row+8, ...)
    const float* sbias = (const float*)(smem + S_BIAS);
    #pragma unroll
    for (int m = 0; m < 2; m++) {
        int row = m0 + wr0 + m * 16 + (lane >> 2);
        #pragma unroll
        for (int t = 0; t < 8; t++) {
            int col = nc0 + t * 8 + 2 * (lane & 3);
            float b0 = sbias[col], b1 = sbias[col + 1];
            float* basep = (col < HH) ? g_xl1 : g_xr1;
            int    cc    = (col < HH) ? col : col - HH;
            if (row < N_NODES) {
                float2 v = make_float2(acc[m][t][0] + b0, acc[m][t][1] + b1);
                *reinterpret_cast<float2*>(basep + (size_t)row * HH + cc) = v;
            }
            if (row + 8 < N_NODES) {
                float2 v = make_float2(acc[m][t][2] + b0, acc[m][t][3] + b1);
                *reinterpret_cast<float2*>(basep + (size_t)(row + 8) * HH + cc) = v;
            }
        }
    }
}

// ---------------- K2: layer-1 edge pass --------------------------------------
__global__ void edge1_kernel(const void* __restrict__ ei, int E,
                             const float* __restrict__ att)
{
    const int E2    = E + N_NODES;
    const int gid   = blockIdx.x * blockDim.x + threadIdx.x;
    const int h     = gid & 7;
    const int lanes = (gridDim.x * blockDim.x) >> 3;

    const float4* at = reinterpret_cast<const float4*>(att + h * 8);
    const float4 t0 = at[0], t1 = at[1];
    const int idx64 = g_idx64;

    for (int eid = gid >> 3; eid < E2; eid += lanes) {
        int s, d;
        load_edge(ei, E, eid, idx64, s, d);
        if ((unsigned)s >= N_NODES || (unsigned)d >= N_NODES) continue;

        const float4* xa = reinterpret_cast<const float4*>(g_xl1 + (size_t)s * HH + h * 8);
        const float4* xb = reinterpret_cast<const float4*>(g_xr1 + (size_t)d * HH + h * 8);
        float4 a0 = xa[0], a1 = xa[1];
        float4 b0 = xb[0], b1 = xb[1];

        float e = lrelu(a0.x + b0.x) * t0.x + lrelu(a0.y + b0.y) * t0.y
                + lrelu(a0.z + b0.z) * t0.z + lrelu(a0.w + b0.w) * t0.w
                + lrelu(a1.x + b1.x) * t1.x + lrelu(a1.y + b1.y) * t1.y
                + lrelu(a1.z + b1.z) * t1.z + lrelu(a1.w + b1.w) * t1.w;

        float wgt = expf(e);

        float* accp = g_acc1 + (size_t)d * HH + h * 8;
        red_add_v4(accp,     wgt * a0.x, wgt * a0.y, wgt * a0.z, wgt * a0.w);
        red_add_v4(accp + 4, wgt * a1.x, wgt * a1.y, wgt * a1.z, wgt * a1.w);
        red_add_f32(g_den1 + (size_t)d * HEADS + h, wgt);
    }
}

// ---------------- K3: finalize L1 + proj2, 16 nodes/block --------------------
__global__ __launch_bounds__(256) void fin1_kernel(
    const float* __restrict__ bias1,
    const float* __restrict__ Wl2, const float* __restrict__ bl2,
    const float* __restrict__ Wr2, const float* __restrict__ br2)
{
    __shared__ float sh[16 * HH];
    __shared__ float sW[HH * 14];
    __shared__ float sbv[14];
    const int tid = threadIdx.x;

    for (int i = tid; i < HH * 14; i += 256) {
        int k = i / 14, j = i - k * 14;
        sW[i] = (j < NCLS) ? Wl2[k * NCLS + j] : Wr2[k * NCLS + (j - NCLS)];
    }
    if (tid < 14) sbv[tid] = (tid < NCLS) ? bl2[tid] : br2[tid - NCLS];

    const int node0 = blockIdx.x * 16;
    const size_t base = (size_t)node0 * HH;
    #pragma unroll
    for (int i = 0; i < 4; i++) {
        int idx = tid + i * 256;
        int f = idx & 63, nd = idx >> 6;
        float v = g_acc1[base + idx] / g_den1[(size_t)(node0 + nd) * HEADS + (f >> 3)] + bias1[f];
        sh[idx] = (v > 0.f) ? v : expm1f(v);    // ELU
    }
    __syncthreads();

    if (tid < 224) {
        int nd = tid / 14, j = tid - nd * 14;
        float acc = sbv[j];
        const float* hrow = sh + nd * HH;
        #pragma unroll
        for (int k = 0; k < HH; k++) acc += hrow[k] * sW[k * 14 + j];
        int n = node0 + nd;
        if (j < NCLS) g_xl2[(size_t)n * 8 + j] = acc;
        else          g_xr2[(size_t)n * 8 + (j - NCLS)] = acc;
    }
}

// ---------------- K4: layer-2 edge pass --------------------------------------
__global__ void edge2_kernel(const void* __restrict__ ei, int E,
                             const float* __restrict__ att2)
{
    const int E2    = E + N_NODES;
    const int lanes = gridDim.x * blockDim.x;
    const int gid   = blockIdx.x * blockDim.x + threadIdx.x;

    float a2[NCLS];
    #pragma unroll
    for (int c = 0; c < NCLS; c++) a2[c] = att2[c];
    const int idx64 = g_idx64;

    for (int eid = gid; eid < E2; eid += lanes) {
        int s, d;
        load_edge(ei, E, eid, idx64, s, d);
        if ((unsigned)s >= N_NODES || (unsigned)d >= N_NODES) continue;

        const float4* xa = reinterpret_cast<const float4*>(g_xl2 + (size_t)s * 8);
        const float4* xb = reinterpret_cast<const float4*>(g_xr2 + (size_t)d * 8);
        float4 p0 = xa[0], p1 = xa[1];
        float4 q0 = xb[0], q1 = xb[1];

        float e = lrelu(p0.x + q0.x) * a2[0] + lrelu(p0.y + q0.y) * a2[1]
                + lrelu(p0.z + q0.z) * a2[2] + lrelu(p0.w + q0.w) * a2[3]
                + lrelu(p1.x + q1.x) * a2[4] + lrelu(p1.y + q1.y) * a2[5]
                + lrelu(p1.z + q1.z) * a2[6];

        float wgt = expf(e);

        float* accp = g_acc2 + (size_t)d * 8;
        red_add_v4(accp,     wgt * p0.x, wgt * p0.y, wgt * p0.z, wgt * p0.w);
        red_add_v4(accp + 4, wgt * p1.x, wgt * p1.y, wgt * p1.z, wgt);   // slot 7: denom
    }
}

// ---------------- K5: final divide + bias + log_softmax ----------------------
__global__ void final_kernel(float* __restrict__ out, const float* __restrict__ bias2)
{
    int n = blockIdx.x * blockDim.x + threadIdx.x;
    if (n >= N_NODES) return;

    const float4* ap = reinterpret_cast<const float4*>(g_acc2 + (size_t)n * 8);
    float4 a0 = ap[0], a1 = ap[1];
    float inv = 1.f / a1.w;

    float v[NCLS];
    v[0] = a0.x * inv + bias2[0];
    v[1] = a0.y * inv + bias2[1];
    v[2] = a0.z * inv + bias2[2];
    v[3] = a0.w * inv + bias2[3];
    v[4] = a1.x * inv + bias2[4];
    v[5] = a1.y * inv + bias2[5];
    v[6] = a1.z * inv + bias2[6];

    float m = v[0];
    #pragma unroll
    for (int c = 1; c < NCLS; c++) m = fmaxf(m, v[c]);
    float ssum = 0.f;
    #pragma unroll
    for (int c = 0; c < NCLS; c++) ssum += expf(v[c] - m);
    float l = m + logf(ssum);
    #pragma unroll
    for (int c = 0; c < NCLS; c++) out[(size_t)n * NCLS + c] = v[c] - l;
}

// ---------------- launch -----------------------------------------------------
extern "C" void kernel_launch(void* const* d_in, const int* in_sizes, int n_in,
                              void* d_out, int out_size)
{
    const float* x     = (const float*)d_in[0];
    const void*  ei    = d_in[1];
    const float* Wl1   = (const float*)d_in[2];
    const float* bl1   = (const float*)d_in[3];
    const float* Wr1   = (const float*)d_in[4];
    const float* br1   = (const float*)d_in[5];
    const float* att1  = (const float*)d_in[6];
    const float* bias1 = (const float*)d_in[7];
    const float* Wl2   = (const float*)d_in[8];
    const float* bl2   = (const float*)d_in[9];
    const float* Wr2   = (const float*)d_in[10];
    const float* br2   = (const float*)d_in[11];
    const float* att2  = (const float*)d_in[12];
    const float* bias2 = (const float*)d_in[13];

    const int E = in_sizes[1] / 2;           // 1,600,000

    cudaFuncSetAttribute(proj1_kernel,
                         cudaFuncAttributeMaxDynamicSharedMemorySize, PROJ_SMEM);

    zero_kernel<<<(N_NODES * 16 + 255) / 256, 256>>>((const int*)ei);
    prepB_kernel<<<(128 * FEAT + 255) / 256, 256>>>(Wl1, Wr1);
    proj1_kernel<<<(N_NODES + 63) / 64, 128, PROJ_SMEM>>>(x, bl1, br1);
    edge1_kernel<<<1184, 256>>>(ei, E, att1);
    fin1_kernel<<<N_NODES / 16, 256>>>(bias1, Wl2, bl2, Wr2, br2);
    edge2_kernel<<<1184, 256>>>(ei, E, att2);
    final_kernel<<<(N_NODES + 255) / 256, 256>>>((float*)d_out, bias2);
}

// round 7
// speedup vs baseline: 1.8302x; 1.0955x over previous
#include <cuda_runtime.h>
#include <cuda_bf16.h>
#include <cstdint>
#include <math.h>

#define N_NODES 50000
#define FEAT    512
#define HH      64      // HEADS*HID
#define HEADS   8
#define NCLS    7
#define E_MAX   1700000

typedef unsigned long long u64;
typedef unsigned int u32;

// ---------------- scratch (device globals: no allocations allowed) ----------
__device__ float g_xl1[N_NODES * HH];
__device__ float g_xr1[N_NODES * HH];
__device__ float g_acc1[N_NODES * HH];
__device__ float g_den1[N_NODES * HEADS];
__device__ float g_xl2[N_NODES * 8];
__device__ float g_xr2[N_NODES * 8];
__device__ float g_acc2[N_NODES * 8];
__device__ int   g_idx64;
// bf16 hi/lo images of B = [Wl | Wr], layout [n][k]
__device__ __nv_bfloat16 g_Bh[128 * FEAT];
__device__ __nv_bfloat16 g_Bl[128 * FEAT];
// CSR (dst-bucketed)
__device__ int g_deg[N_NODES];     // in-degree (incl. self-loop)
__device__ int g_start[N_NODES];   // segment start
__device__ int g_pos[N_NODES];     // scatter cursors
__device__ int g_srcs[E_MAX];      // src node per sorted edge

// ---------------- generic helpers -------------------------------------------
__device__ __forceinline__ float lrelu(float v) { return fmaxf(v, 0.2f * v); }

__device__ __forceinline__ void load_edge(const void* ei, int E, int eid,
                                          int idx64, int& s, int& d) {
    if (eid < E) {
        if (idx64) {
            s = (int)((const long long*)ei)[eid];
            d = (int)((const long long*)ei)[E + eid];
        } else {
            s = ((const int*)ei)[eid];
            d = ((const int*)ei)[E + eid];
        }
    } else {
        s = d = eid - E;
    }
}

__device__ __forceinline__ u32 smem_u32(const void* p) {
    u32 a;
    asm("{ .reg .u64 t; cvta.to.shared.u64 t, %1; cvt.u32.u64 %0, t; }" : "=r"(a) : "l"(p));
    return a;
}

__device__ __forceinline__ void ldsm_x4(u32 addr, u32& r0, u32& r1, u32& r2, u32& r3) {
    asm volatile("ldmatrix.sync.aligned.m8n8.x4.shared.b16 {%0,%1,%2,%3}, [%4];"
                 : "=r"(r0), "=r"(r1), "=r"(r2), "=r"(r3) : "r"(addr));
}

__device__ __forceinline__ void mma_bf16(float* c, const u32* a, const u32* b) {
    asm volatile("mma.sync.aligned.m16n8k16.row.col.f32.bf16.bf16.f32 "
                 "{%0,%1,%2,%3}, {%4,%5,%6,%7}, {%8,%9}, {%0,%1,%2,%3};"
                 : "+f"(c[0]), "+f"(c[1]), "+f"(c[2]), "+f"(c[3])
                 : "r"(a[0]), "r"(a[1]), "r"(a[2]), "r"(a[3]), "r"(b[0]), "r"(b[1]));
}

// ---------------- K0: zero degree array (+ dtype probe) ----------------------
__global__ void zero_kernel(const int* __restrict__ ei_words) {
    int i = blockIdx.x * blockDim.x + threadIdx.x;
    if (i == 0) {
        int all_zero = 1;
        #pragma unroll
        for (int j = 0; j < 64; j++)
            if (ei_words[2 * j + 1] != 0) { all_zero = 0; break; }
        g_idx64 = all_zero;
    }
    if (i < N_NODES) g_deg[i] = 0;
}

// ---------------- CSR build: histogram ---------------------------------------
__global__ void hist_kernel(const void* __restrict__ ei, int E) {
    int eid = blockIdx.x * blockDim.x + threadIdx.x;
    int E2 = E + N_NODES;
    if (eid >= E2) return;
    int s, d;
    load_edge(ei, E, eid, g_idx64, s, d);
    if ((unsigned)d < N_NODES) atomicAdd(&g_deg[d], 1);
}

// ---------------- CSR build: single-block exclusive scan ----------------------
__global__ __launch_bounds__(1024) void scan_kernel() {
    __shared__ int wsum[32];
    __shared__ int carry_s;
    const int tid = threadIdx.x, lane = tid & 31, wid = tid >> 5;
    if (tid == 0) carry_s = 0;
    __syncthreads();
    for (int base = 0; base < N_NODES; base += 1024) {
        int idx = base + tid;
        int v = (idx < N_NODES) ? g_deg[idx] : 0;
        int s = v;
        #pragma unroll
        for (int o = 1; o < 32; o <<= 1) {
            int t = __shfl_up_sync(0xFFFFFFFF, s, o);
            if (lane >= o) s += t;
        }
        if (lane == 31) wsum[wid] = s;
        __syncthreads();
        if (wid == 0) {
            int ws = wsum[lane];
            #pragma unroll
            for (int o = 1; o < 32; o <<= 1) {
                int t = __shfl_up_sync(0xFFFFFFFF, ws, o);
                if (lane >= o) ws += t;
            }
            wsum[lane] = ws;
        }
        __syncthreads();
        int excl = s - v + (wid > 0 ? wsum[wid - 1] : 0) + carry_s;
        if (idx < N_NODES) { g_start[idx] = excl; g_pos[idx] = excl; }
        __syncthreads();               // everyone has read carry_s
        if (tid == 1023) carry_s += wsum[31];
        __syncthreads();
    }
}

// ---------------- CSR build: scatter src ids ---------------------------------
__global__ void scatter_kernel(const void* __restrict__ ei, int E) {
    int eid = blockIdx.x * blockDim.x + threadIdx.x;
    int E2 = E + N_NODES;
    if (eid >= E2) return;
    int s, d;
    load_edge(ei, E, eid, g_idx64, s, d);
    if ((unsigned)s >= N_NODES || (unsigned)d >= N_NODES) return;
    int p = atomicAdd(&g_pos[d], 1);
    g_srcs[p] = s;
}

// ---------------- Kp: build bf16 hi/lo images of [Wl|Wr] as [n][k] ----------
__global__ void prepB_kernel(const float* __restrict__ Wl, const float* __restrict__ Wr) {
    int i = blockIdx.x * blockDim.x + threadIdx.x;
    if (i >= 128 * FEAT) return;
    int n = i >> 9;
    int k = i & 511;
    float w = (n < HH) ? Wl[k * HH + n] : Wr[k * HH + (n - HH)];
    __nv_bfloat16 hi = __float2bfloat16(w);
    __nv_bfloat16 lo = __float2bfloat16(w - __bfloat162float(hi));
    g_Bh[i] = hi;
    g_Bl[i] = lo;
}

// ---------------- K1: proj1 via mma.sync bf16x3 (unchanged from R6) ----------
#define ASTR 72
#define BSTR 72
#define S_AH 0
#define S_AL 9216
#define S_BH 18432
#define S_BL 36864
#define S_BIAS 55296
#define PROJ_SMEM (55296 + 512)

__global__ __launch_bounds__(128) void proj1_kernel(
    const float* __restrict__ x,
    const float* __restrict__ bl, const float* __restrict__ br)
{
    extern __shared__ __align__(16) char smem[];
    const u32 sb = smem_u32(smem);
    const int tid  = threadIdx.x;
    const int lane = tid & 31;
    const int w    = tid >> 5;
    const int m0   = blockIdx.x * 64;

    ((float*)(smem + S_BIAS))[tid] = (tid < HH) ? bl[tid] : br[tid - HH];

    float acc[2][8][4];
    #pragma unroll
    for (int m = 0; m < 2; m++)
        #pragma unroll
        for (int t = 0; t < 8; t++)
            #pragma unroll
            for (int j = 0; j < 4; j++) acc[m][t][j] = 0.f;

    const int wr0 = (w & 1) * 32;
    const int nc0 = (w >> 1) * 64;
    const int r   = lane & 7;
    const int bq  = lane >> 3;
    const u32 offA = (u32)(((wr0 + (bq & 1) * 8 + r) * ASTR + (bq >> 1) * 8) * 2);
    const u32 offB = (u32)(((nc0 + (bq >> 1) * 8 + r) * BSTR + (bq & 1) * 8) * 2);

    for (int c = 0; c < 8; c++) {
        #pragma unroll
        for (int i = 0; i < 8; i++) {
            int idx = tid + i * 128;
            int row = idx >> 4;
            int kq  = (idx & 15) * 4;
            float4 v = make_float4(0.f, 0.f, 0.f, 0.f);
            if (m0 + row < N_NODES)
                v = *reinterpret_cast<const float4*>(x + (size_t)(m0 + row) * FEAT + c * 64 + kq);
            __nv_bfloat162 h01 = __floats2bfloat162_rn(v.x, v.y);
            __nv_bfloat162 h23 = __floats2bfloat162_rn(v.z, v.w);
            __nv_bfloat162 l01 = __floats2bfloat162_rn(v.x - __bfloat162float(h01.x),
                                                       v.y - __bfloat162float(h01.y));
            __nv_bfloat162 l23 = __floats2bfloat162_rn(v.z - __bfloat162float(h23.x),
                                                       v.w - __bfloat162float(h23.y));
            u32 off = (u32)((row * ASTR + kq) * 2);
            *reinterpret_cast<__nv_bfloat162*>(smem + S_AH + off)     = h01;
            *reinterpret_cast<__nv_bfloat162*>(smem + S_AH + off + 4) = h23;
            *reinterpret_cast<__nv_bfloat162*>(smem + S_AL + off)     = l01;
            *reinterpret_cast<__nv_bfloat162*>(smem + S_AL + off + 4) = l23;
        }
        #pragma unroll
        for (int i = 0; i < 8; i++) {
            int idx = tid + i * 128;
            int n   = idx >> 3;
            int kq  = (idx & 7) * 8;
            uint4 vh = *reinterpret_cast<const uint4*>(g_Bh + (size_t)n * FEAT + c * 64 + kq);
            uint4 vl = *reinterpret_cast<const uint4*>(g_Bl + (size_t)n * FEAT + c * 64 + kq);
            u32 off = (u32)((n * BSTR + kq) * 2);
            *reinterpret_cast<uint4*>(smem + S_BH + off) = vh;
            *reinterpret_cast<uint4*>(smem + S_BL + off) = vl;
        }
        __syncthreads();

        #pragma unroll
        for (int s = 0; s < 4; s++) {
            u32 ah[2][4], al[2][4], bh[8][2], blo[8][2];
            #pragma unroll
            for (int m = 0; m < 2; m++) {
                u32 ao = offA + (u32)((m * 16 * ASTR + s * 16) * 2);
                ldsm_x4(sb + S_AH + ao, ah[m][0], ah[m][1], ah[m][2], ah[m][3]);
                ldsm_x4(sb + S_AL + ao, al[m][0], al[m][1], al[m][2], al[m][3]);
            }
            #pragma unroll
            for (int t = 0; t < 8; t += 2) {
                u32 bo = offB + (u32)((t * 8 * BSTR + s * 16) * 2);
                ldsm_x4(sb + S_BH + bo, bh[t][0], bh[t][1], bh[t + 1][0], bh[t + 1][1]);
                ldsm_x4(sb + S_BL + bo, blo[t][0], blo[t][1], blo[t + 1][0], blo[t + 1][1]);
            }
            #pragma unroll
            for (int m = 0; m < 2; m++)
                #pragma unroll
                for (int t = 0; t < 8; t++) {
                    mma_bf16(acc[m][t], ah[m], bh[t]);
                    mma_bf16(acc[m][t], ah[m], blo[t]);
                    mma_bf16(acc[m][t], al[m], bh[t]);
                }
        }
        __syncthreads();
    }

    const float* sbias = (const float*)(smem + S_BIAS);
    #pragma unroll
    for (int m = 0; m < 2; m++) {
        int row = m0 + wr0 + m * 16 + (lane >> 2);
        #pragma unroll
        for (int t = 0; t < 8; t++) {
            int col = nc0 + t * 8 + 2 * (lane & 3);
            float b0 = sbias[col], b1 = sbias[col + 1];
            float* basep = (col < HH) ? g_xl1 : g_xr1;
            int    cc    = (col < HH) ? col : col - HH;
            if (row < N_NODES) {
                float2 v = make_float2(acc[m][t][0] + b0, acc[m][t][1] + b1);
                *reinterpret_cast<float2*>(basep + (size_t)row * HH + cc) = v;
            }
            if (row + 8 < N_NODES) {
                float2 v = make_float2(acc[m][t][2] + b0, acc[m][t][3] + b1);
                *reinterpret_cast<float2*>(basep + (size_t)(row + 8) * HH + cc) = v;
            }
        }
    }
}

// ---------------- K2: layer-1 aggregation over CSR ---------------------------
// One warp per dst node. lane = (j, h): h = lane&7 (head), j = lane>>3 (edge slot).
// Register accumulation; single shuffle-reduce over j; non-atomic store.
__global__ __launch_bounds__(256) void agg1_kernel(const float* __restrict__ att)
{
    const int wid_g = blockIdx.x * 8 + (threadIdx.x >> 5);   // warp id = node
    const int lane  = threadIdx.x & 31;
    const int h     = lane & 7;
    const int j     = lane >> 3;
    if (wid_g >= N_NODES) return;
    const int n = wid_g;

    const float4* at = reinterpret_cast<const float4*>(att + h * 8);
    const float4 t0 = at[0], t1 = at[1];

    const float4* xb = reinterpret_cast<const float4*>(g_xr1 + (size_t)n * HH + h * 8);
    const float4 b0 = xb[0], b1 = xb[1];

    const int start = g_start[n];
    const int deg   = g_deg[n];

    float4 A0 = make_float4(0.f, 0.f, 0.f, 0.f);
    float4 A1 = make_float4(0.f, 0.f, 0.f, 0.f);
    float den = 0.f;

    for (int i = j; i < deg; i += 4) {
        int src = g_srcs[start + i];
        const float4* xa = reinterpret_cast<const float4*>(g_xl1 + (size_t)src * HH + h * 8);
        float4 a0 = xa[0], a1 = xa[1];

        float e = lrelu(a0.x + b0.x) * t0.x + lrelu(a0.y + b0.y) * t0.y
                + lrelu(a0.z + b0.z) * t0.z + lrelu(a0.w + b0.w) * t0.w
                + lrelu(a1.x + b1.x) * t1.x + lrelu(a1.y + b1.y) * t1.y
                + lrelu(a1.z + b1.z) * t1.z + lrelu(a1.w + b1.w) * t1.w;
        float w = expf(e);

        A0.x += w * a0.x; A0.y += w * a0.y; A0.z += w * a0.z; A0.w += w * a0.w;
        A1.x += w * a1.x; A1.y += w * a1.y; A1.z += w * a1.z; A1.w += w * a1.w;
        den += w;
    }

    // reduce across the 4 edge slots (xor 8 then 16)
    #pragma unroll
    for (int m = 8; m <= 16; m <<= 1) {
        A0.x += __shfl_xor_sync(0xFFFFFFFF, A0.x, m);
        A0.y += __shfl_xor_sync(0xFFFFFFFF, A0.y, m);
        A0.z += __shfl_xor_sync(0xFFFFFFFF, A0.z, m);
        A0.w += __shfl_xor_sync(0xFFFFFFFF, A0.w, m);
        A1.x += __shfl_xor_sync(0xFFFFFFFF, A1.x, m);
        A1.y += __shfl_xor_sync(0xFFFFFFFF, A1.y, m);
        A1.z += __shfl_xor_sync(0xFFFFFFFF, A1.z, m);
        A1.w += __shfl_xor_sync(0xFFFFFFFF, A1.w, m);
        den  += __shfl_xor_sync(0xFFFFFFFF, den,  m);
    }

    if (j == 0) {
        float4* accp = reinterpret_cast<float4*>(g_acc1 + (size_t)n * HH + h * 8);
        accp[0] = A0;
        accp[1] = A1;
        g_den1[(size_t)n * HEADS + h] = den;
    }
}

// ---------------- K3: finalize L1 + proj2, 16 nodes/block --------------------
__global__ __launch_bounds__(256) void fin1_kernel(
    const float* __restrict__ bias1,
    const float* __restrict__ Wl2, const float* __restrict__ bl2,
    const float* __restrict__ Wr2, const float* __restrict__ br2)
{
    __shared__ float sh[16 * HH];
    __shared__ float sW[HH * 14];
    __shared__ float sbv[14];
    const int tid = threadIdx.x;

    for (int i = tid; i < HH * 14; i += 256) {
        int k = i / 14, j = i - k * 14;
        sW[i] = (j < NCLS) ? Wl2[k * NCLS + j] : Wr2[k * NCLS + (j - NCLS)];
    }
    if (tid < 14) sbv[tid] = (tid < NCLS) ? bl2[tid] : br2[tid - NCLS];

    const int node0 = blockIdx.x * 16;
    const size_t base = (size_t)node0 * HH;
    #pragma unroll
    for (int i = 0; i < 4; i++) {
        int idx = tid + i * 256;
        int f = idx & 63, nd = idx >> 6;
        float v = g_acc1[base + idx] / g_den1[(size_t)(node0 + nd) * HEADS + (f >> 3)] + bias1[f];
        sh[idx] = (v > 0.f) ? v : expm1f(v);    // ELU
    }
    __syncthreads();

    if (tid < 224) {
        int nd = tid / 14, j = tid - nd * 14;
        float acc = sbv[j];
        const float* hrow = sh + nd * HH;
        #pragma unroll
        for (int k = 0; k < HH; k++) acc += hrow[k] * sW[k * 14 + j];
        int n = node0 + nd;
        if (j < NCLS) g_xl2[(size_t)n * 8 + j] = acc;
        else          g_xr2[(size_t)n * 8 + (j - NCLS)] = acc;
    }
}

// ---------------- K4: layer-2 aggregation over CSR ---------------------------
// One warp per dst node; one edge per lane; full-warp shuffle reduce.
__global__ __launch_bounds__(256) void agg2_kernel(const float* __restrict__ att2)
{
    const int wid_g = blockIdx.x * 8 + (threadIdx.x >> 5);
    const int lane  = threadIdx.x & 31;
    if (wid_g >= N_NODES) return;
    const int n = wid_g;

    float a2[NCLS];
    #pragma unroll
    for (int c = 0; c < NCLS; c++) a2[c] = att2[c];

    const float4* xb = reinterpret_cast<const float4*>(g_xr2 + (size_t)n * 8);
    const float4 q0 = xb[0], q1 = xb[1];

    const int start = g_start[n];
    const int deg   = g_deg[n];

    float4 P0 = make_float4(0.f, 0.f, 0.f, 0.f);
    float4 P1 = make_float4(0.f, 0.f, 0.f, 0.f);   // .w = denominator

    for (int i = lane; i < deg; i += 32) {
        int src = g_srcs[start + i];
        const float4* xa = reinterpret_cast<const float4*>(g_xl2 + (size_t)src * 8);
        float4 p0 = xa[0], p1 = xa[1];

        float e = lrelu(p0.x + q0.x) * a2[0] + lrelu(p0.y + q0.y) * a2[1]
                + lrelu(p0.z + q0.z) * a2[2] + lrelu(p0.w + q0.w) * a2[3]
                + lrelu(p1.x + q1.x) * a2[4] + lrelu(p1.y + q1.y) * a2[5]
                + lrelu(p1.z + q1.z) * a2[6];
        float w = expf(e);

        P0.x += w * p0.x; P0.y += w * p0.y; P0.z += w * p0.z; P0.w += w * p0.w;
        P1.x += w * p1.x; P1.y += w * p1.y; P1.z += w * p1.z; P1.w += w;
    }

    #pragma unroll
    for (int m = 1; m <= 16; m <<= 1) {
        P0.x += __shfl_xor_sync(0xFFFFFFFF, P0.x, m);
        P0.y += __shfl_xor_sync(0xFFFFFFFF, P0.y, m);
        P0.z += __shfl_xor_sync(0xFFFFFFFF, P0.z, m);
        P0.w += __shfl_xor_sync(0xFFFFFFFF, P0.w, m);
        P1.x += __shfl_xor_sync(0xFFFFFFFF, P1.x, m);
        P1.y += __shfl_xor_sync(0xFFFFFFFF, P1.y, m);
        P1.z += __shfl_xor_sync(0xFFFFFFFF, P1.z, m);
        P1.w += __shfl_xor_sync(0xFFFFFFFF, P1.w, m);
    }

    if (lane == 0) {
        float4* accp = reinterpret_cast<float4*>(g_acc2 + (size_t)n * 8);
        accp[0] = P0;
        accp[1] = P1;
    }
}

// ---------------- K5: final divide + bias + log_softmax ----------------------
__global__ void final_kernel(float* __restrict__ out, const float* __restrict__ bias2)
{
    int n = blockIdx.x * blockDim.x + threadIdx.x;
    if (n >= N_NODES) return;

    const float4* ap = reinterpret_cast<const float4*>(g_acc2 + (size_t)n * 8);
    float4 a0 = ap[0], a1 = ap[1];
    float inv = 1.f / a1.w;

    float v[NCLS];
    v[0] = a0.x * inv + bias2[0];
    v[1] = a0.y * inv + bias2[1];
    v[2] = a0.z * inv + bias2[2];
    v[3] = a0.w * inv + bias2[3];
    v[4] = a1.x * inv + bias2[4];
    v[5] = a1.y * inv + bias2[5];
    v[6] = a1.z * inv + bias2[6];

    float m = v[0];
    #pragma unroll
    for (int c = 1; c < NCLS; c++) m = fmaxf(m, v[c]);
    float ssum = 0.f;
    #pragma unroll
    for (int c = 0; c < NCLS; c++) ssum += expf(v[c] - m);
    float l = m + logf(ssum);
    #pragma unroll
    for (int c = 0; c < NCLS; c++) out[(size_t)n * NCLS + c] = v[c] - l;
}

// ---------------- launch -----------------------------------------------------
extern "C" void kernel_launch(void* const* d_in, const int* in_sizes, int n_in,
                              void* d_out, int out_size)
{
    const float* x     = (const float*)d_in[0];
    const void*  ei    = d_in[1];
    const float* Wl1   = (const float*)d_in[2];
    const float* bl1   = (const float*)d_in[3];
    const float* Wr1   = (const float*)d_in[4];
    const float* br1   = (const float*)d_in[5];
    const float* att1  = (const float*)d_in[6];
    const float* bias1 = (const float*)d_in[7];
    const float* Wl2   = (const float*)d_in[8];
    const float* bl2   = (const float*)d_in[9];
    const float* Wr2   = (const float*)d_in[10];
    const float* br2   = (const float*)d_in[11];
    const float* att2  = (const float*)d_in[12];
    const float* bias2 = (const float*)d_in[13];

    const int E  = in_sizes[1] / 2;          // 1,600,000
    const int E2 = E + N_NODES;

    cudaFuncSetAttribute(proj1_kernel,
                         cudaFuncAttributeMaxDynamicSharedMemorySize, PROJ_SMEM);

    const int nodeWarpBlocks = (N_NODES + 7) / 8;   // 1 warp/node, 8 warps/block

    zero_kernel<<<(N_NODES + 255) / 256, 256>>>((const int*)ei);
    hist_kernel<<<(E2 + 255) / 256, 256>>>(ei, E);
    scan_kernel<<<1, 1024>>>();
    scatter_kernel<<<(E2 + 255) / 256, 256>>>(ei, E);
    prepB_kernel<<<(128 * FEAT + 255) / 256, 256>>>(Wl1, Wr1);
    proj1_kernel<<<(N_NODES + 63) / 64, 128, PROJ_SMEM>>>(x, bl1, br1);
    agg1_kernel<<<nodeWarpBlocks, 256>>>(att1);
    fin1_kernel<<<N_NODES / 16, 256>>>(bias1, Wl2, bl2, Wr2, br2);
    agg2_kernel<<<nodeWarpBlocks, 256>>>(att2);
    final_kernel<<<(N_NODES + 255) / 256, 256>>>((float*)d_out, bias2);
}